// round 1
// baseline (speedup 1.0000x reference)
#include <cuda_runtime.h>

// Problem constants
#define DIM_B 8
#define DIM_C 16
#define DIM_H 512
#define DIM_W 512
#define NFFT  512
#define NIMG  (DIM_B * DIM_C)          // 128 images
#define NROWS (NIMG * DIM_H)           // 65536 row-lines
#define INV_SCALE (1.0f / (512.0f * 512.0f))

// Scratch: full complex intermediate [img][h][w], 256 MB. Device global (no cudaMalloc).
__device__ float2 g_scratch[(size_t)NIMG * DIM_H * DIM_W];
// Baked filter: bit-reversed in both axes, transposed to [w_pos][h_pos], scale folded in. 2 MB.
__device__ float2 g_filter[(size_t)DIM_H * DIM_W];

__device__ __forceinline__ float2 cmul(float2 a, float2 b) {
    return make_float2(a.x * b.x - a.y * b.y, a.x * b.y + a.y * b.x);
}

__device__ __forceinline__ int brev9(int v) {
    return (int)(__brev((unsigned)v) >> 23);
}

// Fill twiddle table tw[k] = exp(-2*pi*i*k/512), k in [0,256)
__device__ __forceinline__ void init_tw(float2* tw, int tid) {
    if (tid < 256) {
        float s, c;
        sincosf(-6.283185307179586f * (float)tid / 512.0f, &s, &c);
        tw[tid] = make_float2(c, s);
    }
}

// 512-point FFT in shared memory; 128 threads (lane in [0,128)), 2 butterflies/thread/stage.
// forward (inv=false): DIF, natural input -> bit-reversed output, exp(-i...)
// inverse (inv=true):  DIT, bit-reversed input -> natural output, exp(+i...), UNSCALED
__device__ __forceinline__ void fft512(float2* a, int lane, const float2* tw, bool inv) {
    if (!inv) {
        #pragma unroll
        for (int s = 0; s < 9; ++s) {
            int m = 256 >> s;                 // half-span
            #pragma unroll
            for (int q = 0; q < 2; ++q) {
                int b = lane + q * 128;       // butterfly id 0..255
                int j = b & (m - 1);
                int i = ((b & ~(m - 1)) << 1) | j;
                float2 u = a[i];
                float2 v = a[i + m];
                float2 sum = make_float2(u.x + v.x, u.y + v.y);
                float2 dif = make_float2(u.x - v.x, u.y - v.y);
                float2 w = tw[j << s];        // exp(-2pi i * j/(2m))
                a[i]     = sum;
                a[i + m] = make_float2(dif.x * w.x - dif.y * w.y,
                                       dif.x * w.y + dif.y * w.x);
            }
            __syncthreads();
        }
    } else {
        #pragma unroll
        for (int s = 0; s < 9; ++s) {
            int m = 1 << s;
            #pragma unroll
            for (int q = 0; q < 2; ++q) {
                int b = lane + q * 128;
                int j = b & (m - 1);
                int i = ((b & ~(m - 1)) << 1) | j;
                float2 w = tw[j << (8 - s)];  // conj applied below => exp(+2pi i * j/(2m))
                float2 v = a[i + m];
                float2 t = make_float2(v.x * w.x + v.y * w.y,
                                       v.y * w.x - v.x * w.y);
                float2 u = a[i];
                a[i]     = make_float2(u.x + t.x, u.y + t.y);
                a[i + m] = make_float2(u.x - t.x, u.y - t.y);
            }
            __syncthreads();
        }
    }
}

// ---------------------------------------------------------------------------
// Kernel 0: bake filter into bit-reversed / transposed / pre-scaled table.
// g_filter[pw*512 + ph] = (Hr + i*Hi)[brev(ph)][brev(pw)] * (1/(512*512))
// ---------------------------------------------------------------------------
__global__ void k_bake_filter(const float* __restrict__ Hr, const float* __restrict__ Hi) {
    int i = blockIdx.x * blockDim.x + threadIdx.x;  // 0 .. 262143
    int pw = i >> 9;
    int ph = i & 511;
    int src = brev9(ph) * 512 + brev9(pw);
    g_filter[i] = make_float2(Hr[src] * INV_SCALE, Hi[src] * INV_SCALE);
}

// ---------------------------------------------------------------------------
// Kernel 1: forward FFT along W for every row line (4 lines/block, 512 thr).
// ---------------------------------------------------------------------------
__global__ void __launch_bounds__(512) k_fft_rows(const float* __restrict__ x) {
    __shared__ float2 sd[4][NFFT];
    __shared__ float2 tw[256];
    int tid = threadIdx.x;
    init_tw(tw, tid);
    int slot = tid >> 7;
    int lane = tid & 127;
    long long row = (long long)blockIdx.x * 4 + slot;
    const float* xp = x + row * NFFT;

    #pragma unroll
    for (int k = 0; k < 4; ++k) {
        int idx = lane + k * 128;
        sd[slot][idx] = make_float2(xp[idx], 0.0f);
    }
    __syncthreads();

    fft512(sd[slot], lane, tw, false);   // ends with __syncthreads

    float2* gp = g_scratch + row * NFFT;
    #pragma unroll
    for (int k = 0; k < 4; ++k) {
        int idx = lane + k * 128;
        gp[idx] = sd[slot][idx];
    }
}

// ---------------------------------------------------------------------------
// Kernel 2: per image, per 4-column group: FFT along H (DIF), multiply by
// baked filter (bit-reversed coords on both axes), inverse FFT along H (DIT).
// ---------------------------------------------------------------------------
__global__ void __launch_bounds__(512) k_cols(void) {
    __shared__ float2 sd[4][NFFT];
    __shared__ float2 tw[256];
    int tid = threadIdx.x;
    init_tw(tw, tid);

    int img = blockIdx.x >> 7;            // 0..127
    int w0  = (blockIdx.x & 127) << 2;    // column group base

    // Coalesced-ish strided load: 4 adjacent columns so each 32B sector is full.
    int wi = tid & 3;
    int h0 = tid >> 2;                    // 0..127
    float2* base = g_scratch + (long long)img * DIM_H * DIM_W + w0 + wi;
    #pragma unroll
    for (int k = 0; k < 4; ++k) {
        int h = h0 + k * 128;
        sd[wi][h] = base[(long long)h * DIM_W];
    }
    __syncthreads();

    int slot = tid >> 7;
    int lane = tid & 127;
    fft512(sd[slot], lane, tw, false);

    // Pointwise filter, coalesced read of baked table [w_pos][h_pos].
    const float2* frow = g_filter + (long long)(w0 + slot) * 512;
    #pragma unroll
    for (int k = 0; k < 4; ++k) {
        int p = lane + k * 128;
        sd[slot][p] = cmul(sd[slot][p], frow[p]);
    }
    __syncthreads();

    fft512(sd[slot], lane, tw, true);

    #pragma unroll
    for (int k = 0; k < 4; ++k) {
        int h = h0 + k * 128;
        base[(long long)h * DIM_W] = sd[wi][h];
    }
}

// ---------------------------------------------------------------------------
// Kernel 3: inverse FFT along W for every row line, write real part.
// ---------------------------------------------------------------------------
__global__ void __launch_bounds__(512) k_ifft_rows(float* __restrict__ out) {
    __shared__ float2 sd[4][NFFT];
    __shared__ float2 tw[256];
    int tid = threadIdx.x;
    init_tw(tw, tid);
    int slot = tid >> 7;
    int lane = tid & 127;
    long long row = (long long)blockIdx.x * 4 + slot;
    const float2* gp = g_scratch + row * NFFT;

    #pragma unroll
    for (int k = 0; k < 4; ++k) {
        int idx = lane + k * 128;
        sd[slot][idx] = gp[idx];
    }
    __syncthreads();

    fft512(sd[slot], lane, tw, true);

    float* op = out + row * NFFT;
    #pragma unroll
    for (int k = 0; k < 4; ++k) {
        int idx = lane + k * 128;
        op[idx] = sd[slot][idx].x;
    }
}

// ---------------------------------------------------------------------------
extern "C" void kernel_launch(void* const* d_in, const int* in_sizes, int n_in,
                              void* d_out, int out_size) {
    const float* x  = (const float*)d_in[0];   // [8,16,512,512]
    const float* Hr = (const float*)d_in[1];   // [512,512]
    const float* Hi = (const float*)d_in[2];   // [512,512]
    float* out = (float*)d_out;

    k_bake_filter<<<(DIM_H * DIM_W) / 512, 512>>>(Hr, Hi);
    k_fft_rows<<<NROWS / 4, 512>>>(x);
    k_cols<<<NIMG * (DIM_W / 4), 512>>>();
    k_ifft_rows<<<NROWS / 4, 512>>>(out);
}